// round 4
// baseline (speedup 1.0000x reference)
#include <cuda_runtime.h>
#include <stdint.h>

// ScaledNeuron: IF neuron, soft reset, V_TH=1.0, SCALE=1.0, v0=0.5.
// xs: [B=16, C=64, H=64, W=64, T=8] fp32, T contiguous.
// Pure HBM stream. Per thread: 2 spatial locations = 4x LDG.128 (front-batched,
// streaming) + 4x STG.128 (streaming). 268 MB total traffic, zero reuse.

static constexpr int T = 8;

__device__ __forceinline__ void if_step(const float4& a, const float4& b,
                                        float4& oa, float4& ob) {
    float x[T] = {a.x, a.y, a.z, a.w, b.x, b.y, b.z, b.w};
    float s[T];
    float v = 0.5f;
#pragma unroll
    for (int t = 0; t < T; t++) {
        v += x[t];
        float sp = (v >= 1.0f) ? 1.0f : 0.0f;
        v -= sp;
        s[t] = sp;
    }
    oa = make_float4(s[0], s[1], s[2], s[3]);
    ob = make_float4(s[4], s[5], s[6], s[7]);
}

__global__ __launch_bounds__(256)
void scaled_neuron_kernel(const float4* __restrict__ in,
                          float4* __restrict__ out,
                          int n_pairs) {
    // Each "pair" = 2 spatial locations = 4 float4 (64 bytes).
    int i = blockIdx.x * blockDim.x + threadIdx.x;
    if (i >= n_pairs) return;

    long long base = 4LL * i;

    // Front-batch all 4 streaming loads (MLP_p1 = 4).
    float4 a0 = __ldcs(in + base + 0);
    float4 b0 = __ldcs(in + base + 1);
    float4 a1 = __ldcs(in + base + 2);
    float4 b1 = __ldcs(in + base + 3);

    float4 oa0, ob0, oa1, ob1;
    if_step(a0, b0, oa0, ob0);
    if_step(a1, b1, oa1, ob1);

    __stcs(out + base + 0, oa0);
    __stcs(out + base + 1, ob0);
    __stcs(out + base + 2, oa1);
    __stcs(out + base + 3, ob1);
}

extern "C" void kernel_launch(void* const* d_in, const int* in_sizes, int n_in,
                              void* d_out, int out_size) {
    const float4* in = (const float4*)d_in[0];
    float4* out = (float4*)d_out;

    int n_loc = in_sizes[0] / T;          // spatial locations (4,194,304)
    int n_pairs = n_loc / 2;              // 2 locations per thread (n_loc is even)
    int threads = 256;
    int blocks = (n_pairs + threads - 1) / threads;

    scaled_neuron_kernel<<<blocks, threads>>>(in, out, n_pairs);
}

// round 5
// speedup vs baseline: 1.0142x; 1.0142x over previous
#include <cuda_runtime.h>
#include <stdint.h>

// ScaledNeuron: IF neuron, soft reset, V_TH=1.0, SCALE=1.0, v0=0.5.
// xs: [B=16, C=64, H=64, W=64, T=8] fp32, T contiguous.
// Pure HBM stream. Per thread: 2 spatial locations = 4x LDG.128 front-batched
// + 4x STG.128. DEFAULT cache policy (R3 showed .cs hurts L2 writeback).

static constexpr int T = 8;

__device__ __forceinline__ void if_step(const float4& a, const float4& b,
                                        float4& oa, float4& ob) {
    float x[T] = {a.x, a.y, a.z, a.w, b.x, b.y, b.z, b.w};
    float s[T];
    float v = 0.5f;
#pragma unroll
    for (int t = 0; t < T; t++) {
        v += x[t];
        float sp = (v >= 1.0f) ? 1.0f : 0.0f;
        v -= sp;
        s[t] = sp;
    }
    oa = make_float4(s[0], s[1], s[2], s[3]);
    ob = make_float4(s[4], s[5], s[6], s[7]);
}

__global__ __launch_bounds__(256)
void scaled_neuron_kernel(const float4* __restrict__ in,
                          float4* __restrict__ out,
                          int n_pairs) {
    // Each "pair" = 2 spatial locations = 4 float4 (64 bytes).
    int i = blockIdx.x * blockDim.x + threadIdx.x;
    if (i >= n_pairs) return;

    long long base = 4LL * i;

    // Front-batch all 4 loads (MLP_p1 = 4), default cache policy.
    float4 a0 = in[base + 0];
    float4 b0 = in[base + 1];
    float4 a1 = in[base + 2];
    float4 b1 = in[base + 3];

    float4 oa0, ob0, oa1, ob1;
    if_step(a0, b0, oa0, ob0);
    if_step(a1, b1, oa1, ob1);

    out[base + 0] = oa0;
    out[base + 1] = ob0;
    out[base + 2] = oa1;
    out[base + 3] = ob1;
}

extern "C" void kernel_launch(void* const* d_in, const int* in_sizes, int n_in,
                              void* d_out, int out_size) {
    const float4* in = (const float4*)d_in[0];
    float4* out = (float4*)d_out;

    int n_loc = in_sizes[0] / T;          // spatial locations (4,194,304)
    int n_pairs = n_loc / 2;              // 2 locations per thread
    int threads = 256;
    int blocks = (n_pairs + threads - 1) / threads;

    scaled_neuron_kernel<<<blocks, threads>>>(in, out, n_pairs);
}

// round 6
// speedup vs baseline: 1.0189x; 1.0046x over previous
#include <cuda_runtime.h>
#include <stdint.h>

// ScaledNeuron: IF neuron, soft reset, V_TH=1.0, SCALE=1.0, v0=0.5.
// xs: [B=16, C=64, H=64, W=64, T=8] fp32, T contiguous.
//
// Fully-coalesced stream via smem transpose:
//  - 256 threads/block, 256 locations/block = 512 float4 = 8 KB per direction.
//  - Load phase: buf_in[t] = in[base+t], buf_in[256+t] = in[base+256+t]
//    -> every warp LDG.128 covers 512 contiguous bytes (4 fully-used lines).
//  - Compute phase: thread t reads its location's pair from smem (LDS, 2-way
//    conflict, non-binding), runs the 8-step IF recurrence, writes results
//    into buf_out.
//  - Store phase: coalesced STG from buf_out.

static constexpr int T = 8;
static constexpr int THREADS = 256;

__global__ __launch_bounds__(THREADS)
void scaled_neuron_kernel(const float4* __restrict__ in,
                          float4* __restrict__ out,
                          int n_loc) {
    __shared__ float4 buf_in[2 * THREADS];
    __shared__ float4 buf_out[2 * THREADS];

    int t = threadIdx.x;
    long long base = 2LL * THREADS * blockIdx.x;  // float4 index of block start

    // Guard: grid sized so every block is full (n_loc % THREADS == 0 here,
    // n_loc = 4,194,304). Keep a safe check anyway.
    long long loc0 = (long long)blockIdx.x * THREADS;
    if (loc0 >= n_loc) return;

    // ---- coalesced load into smem ----
    buf_in[t]           = in[base + t];
    buf_in[THREADS + t] = in[base + THREADS + t];
    __syncthreads();

    // ---- per-location IF recurrence ----
    float4 a = buf_in[2 * t];
    float4 b = buf_in[2 * t + 1];

    float x[T] = {a.x, a.y, a.z, a.w, b.x, b.y, b.z, b.w};
    float s[T];
    float v = 0.5f;
#pragma unroll
    for (int k = 0; k < T; k++) {
        v += x[k];
        float sp = (v >= 1.0f) ? 1.0f : 0.0f;
        v -= sp;
        s[k] = sp;
    }

    buf_out[2 * t]     = make_float4(s[0], s[1], s[2], s[3]);
    buf_out[2 * t + 1] = make_float4(s[4], s[5], s[6], s[7]);
    __syncthreads();

    // ---- coalesced store from smem ----
    out[base + t]           = buf_out[t];
    out[base + THREADS + t] = buf_out[THREADS + t];
}

extern "C" void kernel_launch(void* const* d_in, const int* in_sizes, int n_in,
                              void* d_out, int out_size) {
    const float4* in = (const float4*)d_in[0];
    float4* out = (float4*)d_out;

    int n_loc = in_sizes[0] / T;  // 4,194,304 spatial locations
    int blocks = (n_loc + THREADS - 1) / THREADS;  // 16384

    scaled_neuron_kernel<<<blocks, THREADS>>>(in, out, n_loc);
}

// round 7
// speedup vs baseline: 1.0638x; 1.0441x over previous
#include <cuda_runtime.h>
#include <stdint.h>

// ScaledNeuron: IF neuron, soft reset, V_TH=1.0, SCALE=1.0, v0=0.5.
// xs: [B=16, C=64, H=64, W=64, T=8] fp32, T contiguous.
//
// Perfect-coalescing scheme: ONE float4 (= 4 timesteps of one location) per
// thread. Lane 2k holds t0..3 of location, lane 2k+1 holds t4..7 of the SAME
// location. Recurrence stitched across the lane pair with one shfl:
//   pass 1: all lanes run 4 IF steps from v=0.5  (valid for even lanes)
//   shfl_up(v,1): odd lane receives even lane's v after t3
//   pass 2: odd lanes re-run 4 IF steps from that v (valid for t4..7)
// Both LDG.128 and STG.128 are 16B/lane consecutive -> minimal L1 wavefronts.

__device__ __forceinline__ float4 if4(float4 x, float& v) {
    float s0, s1, s2, s3;
    v += x.x; s0 = (v >= 1.0f) ? 1.0f : 0.0f; v -= s0;
    v += x.y; s1 = (v >= 1.0f) ? 1.0f : 0.0f; v -= s1;
    v += x.z; s2 = (v >= 1.0f) ? 1.0f : 0.0f; v -= s2;
    v += x.w; s3 = (v >= 1.0f) ? 1.0f : 0.0f; v -= s3;
    return make_float4(s0, s1, s2, s3);
}

__global__ __launch_bounds__(256)
void scaled_neuron_kernel(const float4* __restrict__ in,
                          float4* __restrict__ out,
                          int n4) {
    int i = blockIdx.x * blockDim.x + threadIdx.x;  // float4 index
    if (i >= n4) return;

    float4 x = in[i];

    // Pass 1: valid result for even float4 indices (t0..3 of a location).
    float v = 0.5f;
    float4 s = if4(x, v);

    // Hand v (after t3) from even lane to its odd partner.
    // blockDim=256 and grid offset are even, so parity(i) == parity(lane).
    float v4 = __shfl_up_sync(0xffffffffu, v, 1);

    if (threadIdx.x & 1) {
        float vv = v4;
        s = if4(x, vv);  // Pass 2: t4..7 starting from partner's v.
    }

    out[i] = s;
}

extern "C" void kernel_launch(void* const* d_in, const int* in_sizes, int n_in,
                              void* d_out, int out_size) {
    const float4* in = (const float4*)d_in[0];
    float4* out = (float4*)d_out;

    int n4 = in_sizes[0] / 4;  // 8,388,608 float4
    int threads = 256;
    int blocks = (n4 + threads - 1) / threads;  // 32768

    scaled_neuron_kernel<<<blocks, threads>>>(in, out, n4);
}

// round 8
// speedup vs baseline: 1.1121x; 1.0454x over previous
#include <cuda_runtime.h>
#include <stdint.h>

// ScaledNeuron: IF neuron, soft reset, V_TH=1.0, SCALE=1.0, v0=0.5.
// xs: [B=16, C=64, H=64, W=64, T=8] fp32, T contiguous.
//
// Perfect coalescing (one float4 = half a location per lane; temporal
// recurrence stitched across the even/odd lane pair with shfl_up) PLUS
// MLP=2: each thread handles float4 i and i + n4/2, both loads front-
// batched. Both streams are independently lane-consecutive (16B/lane),
// and n4/2 is even so lane parity == element parity for both.

__device__ __forceinline__ float4 if4(float4 x, float& v) {
    float s0, s1, s2, s3;
    v += x.x; s0 = (v >= 1.0f) ? 1.0f : 0.0f; v -= s0;
    v += x.y; s1 = (v >= 1.0f) ? 1.0f : 0.0f; v -= s1;
    v += x.z; s2 = (v >= 1.0f) ? 1.0f : 0.0f; v -= s2;
    v += x.w; s3 = (v >= 1.0f) ? 1.0f : 0.0f; v -= s3;
    return make_float4(s0, s1, s2, s3);
}

__global__ __launch_bounds__(256)
void scaled_neuron_kernel(const float4* __restrict__ in,
                          float4* __restrict__ out,
                          int half) {           // half = n4 / 2
    int i = blockIdx.x * blockDim.x + threadIdx.x;
    if (i >= half) return;

    // Front-batched, both perfectly coalesced (MLP_p1 = 2).
    float4 x0 = in[i];
    float4 x1 = in[i + half];

    // Pass 1 (valid for even lanes: t0..3 of each location).
    float v0 = 0.5f, v1 = 0.5f;
    float4 s0 = if4(x0, v0);
    float4 s1 = if4(x1, v1);

    // Even lane hands its v-after-t3 to its odd partner.
    float p0 = __shfl_up_sync(0xffffffffu, v0, 1);
    float p1 = __shfl_up_sync(0xffffffffu, v1, 1);

    if (threadIdx.x & 1) {
        float w0 = p0, w1 = p1;
        s0 = if4(x0, w0);   // Pass 2: t4..7 from partner's v.
        s1 = if4(x1, w1);
    }

    out[i]        = s0;
    out[i + half] = s1;
}

extern "C" void kernel_launch(void* const* d_in, const int* in_sizes, int n_in,
                              void* d_out, int out_size) {
    const float4* in = (const float4*)d_in[0];
    float4* out = (float4*)d_out;

    int n4 = in_sizes[0] / 4;   // 8,388,608 float4
    int half = n4 / 2;          // 4,194,304 (even)
    int threads = 256;
    int blocks = (half + threads - 1) / threads;  // 16384

    scaled_neuron_kernel<<<blocks, threads>>>(in, out, half);
}